// round 3
// baseline (speedup 1.0000x reference)
#include <cuda_runtime.h>

// Problem constants
#define B_   8
#define C_   64
#define H_   256
#define W_   256
#define HW_  65536
#define OC_  64
#define P_   16
#define CU_  48      // unselected channels
#define OUTC_ 112

// ---------------- device globals (scratch; no allocations allowed) ----------
__device__ float d_act[B_ * C_];
__device__ int   d_sel[B_ * P_];
__device__ int   d_unsel[B_ * CU_];

// ---------------- f32x2 helpers --------------------------------------------
__device__ __forceinline__ unsigned long long pack2(float lo, float hi) {
    unsigned long long r;
    asm("mov.b64 %0, {%1, %2};" : "=l"(r)
        : "r"(__float_as_uint(lo)), "r"(__float_as_uint(hi)));
    return r;
}
__device__ __forceinline__ void unpack2(unsigned long long v, float& lo, float& hi) {
    unsigned int a, b;
    asm("mov.b64 {%0, %1}, %2;" : "=r"(a), "=r"(b) : "l"(v));
    lo = __uint_as_float(a);
    hi = __uint_as_float(b);
}
__device__ __forceinline__ unsigned long long fma2(unsigned long long a,
                                                   unsigned long long b,
                                                   unsigned long long c) {
    unsigned long long d;
    asm("fma.rn.f32x2 %0, %1, %2, %3;" : "=l"(d) : "l"(a), "l"(b), "l"(c));
    return d;
}

// ---------------- kernel 1: per-channel min/max + histogram + entropy -------
// one block per (b,c) channel; pass 2 re-reads the channel (hot in L2).
__global__ void channel_stats_kernel(const float* __restrict__ x) {
    const int bc  = blockIdx.x;            // 0..511
    const int tid = threadIdx.x;           // 256 threads
    const int lane = tid & 31, wid = tid >> 5;
    const float4* xp = reinterpret_cast<const float4*>(x) + (size_t)bc * (HW_ / 4);

    // ---- pass 1: min / max ----
    float mn = 3.402823466e38f, mx = -3.402823466e38f;
    for (int i = tid; i < HW_ / 4; i += 256) {
        float4 v = xp[i];
        mn = fminf(mn, fminf(fminf(v.x, v.y), fminf(v.z, v.w)));
        mx = fmaxf(mx, fmaxf(fmaxf(v.x, v.y), fmaxf(v.z, v.w)));
    }
    #pragma unroll
    for (int off = 16; off > 0; off >>= 1) {
        mn = fminf(mn, __shfl_xor_sync(0xffffffffu, mn, off));
        mx = fmaxf(mx, __shfl_xor_sync(0xffffffffu, mx, off));
    }
    __shared__ float smn[8], smx[8];
    __shared__ float s_mn, s_rng, s_scale;
    if (lane == 0) { smn[wid] = mn; smx[wid] = mx; }
    __syncthreads();
    if (tid == 0) {
        float m = smn[0], M = smx[0];
        #pragma unroll
        for (int i = 1; i < 8; i++) { m = fminf(m, smn[i]); M = fmaxf(M, smx[i]); }
        s_mn = m;
        float rng = __fadd_rn(__fsub_rn(M, m), 1e-8f);  // (max-min)+eps, IEEE rn
        s_rng = rng;
        s_scale = __fdiv_rn(256.0f, rng);
    }
    __syncthreads();

    // ---- pass 2: histogram (per-warp private, smem atomics) ----
    __shared__ int h[8][256];
    for (int i = tid; i < 8 * 256; i += 256) ((int*)h)[i] = 0;
    __syncthreads();
    const float mnv = s_mn, rng = s_rng, sc = s_scale;
    int* hw = h[wid];
    for (int i = tid; i < HW_ / 4; i += 256) {
        float4 v = xp[i];
        float vals[4] = { v.x, v.y, v.z, v.w };
        #pragma unroll
        for (int k = 0; k < 4; k++) {
            float t = __fsub_rn(vals[k], mnv);
            float a = __fmul_rn(t, sc);                 // fast approx of (t/rng)*256
            int bin = (int)a;
            float fr = a - (float)bin;
            float band = __fmaf_rn(4e-7f, a, 1e-6f);
            if (fr < band || fr > 1.0f - band) {        // near a bin edge: exact path
                a = __fmul_rn(__fdiv_rn(t, rng), 256.0f);  // matches reference (div.rn, *256 exact)
                bin = (int)a;
            }
            if (bin > 255) bin = 255;
            atomicAdd(&hw[bin], 1);
        }
    }
    __syncthreads();

    // ---- entropy ----
    __shared__ float hf[256], red[256];
    {
        int c = 0;
        #pragma unroll
        for (int w2 = 0; w2 < 8; w2++) c += h[w2][tid];
        hf[tid] = (float)c + 1e-8f;                     // hist + eps
    }
    __syncthreads();
    red[tid] = hf[tid];
    __syncthreads();
    for (int st = 128; st > 0; st >>= 1) {
        if (tid < st) red[tid] += red[tid + st];
        __syncthreads();
    }
    __shared__ float s_tot;
    if (tid == 0) s_tot = red[0];
    __syncthreads();
    float p = hf[tid] / s_tot;
    red[tid] = p * logf(p + 1e-8f);
    __syncthreads();
    for (int st = 128; st > 0; st >>= 1) {
        if (tid < st) red[tid] += red[tid + st];
        __syncthreads();
    }
    if (tid == 0) d_act[bc] = -red[0];
}

// ---------------- kernel 2: top-16 (desc, ties -> lowest idx) + unselected --
__global__ void topk_kernel() {
    int b = threadIdx.x;
    if (b >= B_) return;
    float a[C_];
    bool  m[C_];
    for (int c = 0; c < C_; c++) { a[c] = d_act[b * C_ + c]; m[c] = false; }
    for (int k = 0; k < P_; k++) {
        float best = -3.402823466e38f;
        int bi = 0;
        for (int c = 0; c < C_; c++)
            if (!m[c] && a[c] > best) { best = a[c]; bi = c; }
        d_sel[b * P_ + k] = bi;
        m[bi] = true;
    }
    int j = 0;
    for (int c = 0; c < C_; c++)
        if (!m[c]) d_unsel[b * CU_ + (j++)] = c;
}

// ---------------- kernel 3 (fused): conv (f32x2-packed) + untouched copy ----
// blocks [0,384): copy one unselected channel each (memory-bound, overlaps conv)
// blocks [384,1408): conv tiles, 4 rows x 128 cols, 512 threads
//   thread = (ocg = tid&3 -> 16 ocs) x (pg = tid>>2 -> row=pg>>5, wl=pg&31,
//            4 pixels at w = wl + 32*i). acc[4][8] ULL = {oc even, oc odd} pairs.
#define XS_ROWSTRIDE 130
#define XS_CHSTRIDE  (6 * XS_ROWSTRIDE)   // 780
#define XS_FLOATS    (16 * XS_CHSTRIDE)   // 12480
#define WPK_WORDS    (144 * 32)           // 4608
#define CONV_SMEM_BYTES (XS_FLOATS * 4 + WPK_WORDS * 8)  // 86784

__global__ void __launch_bounds__(512, 1)
conv_copy_kernel(const float* __restrict__ x, const float* __restrict__ wgt,
                 const float* __restrict__ bias, float* __restrict__ out) {
    // ---------- copy path ----------
    if (blockIdx.x < B_ * CU_) {
        int id = blockIdx.x;
        int j = id % CU_, b = id / CU_;
        int ch = d_unsel[b * CU_ + j];
        const float4* src = reinterpret_cast<const float4*>(x)
                            + ((size_t)(b * C_ + ch)) * (HW_ / 4);
        float4* dst = reinterpret_cast<float4*>(out)
                      + ((size_t)(b * OUTC_ + OC_ + j)) * (HW_ / 4);
        for (int i = threadIdx.x; i < HW_ / 4; i += 512) dst[i] = src[i];
        return;
    }

    // ---------- conv path ----------
    extern __shared__ float sm[];
    float* xs = sm;                                            // [16][6][130]
    unsigned long long* swpk = (unsigned long long*)(sm + XS_FLOATS); // [144][32]
    __shared__ int ssel[P_];

    int bx = blockIdx.x - B_ * CU_;          // 0..1023
    int ct = bx & 1;                          // col tile (128 wide)
    int rt = (bx >> 1) & 63;                  // row tile (4 high)
    int b  = bx >> 7;
    int r0 = rt * 4, c0 = ct * 128;
    int tid = threadIdx.x;

    if (tid < P_) ssel[tid] = d_sel[b * P_ + tid];
    // pack weights into {oc_even, oc_odd} f32x2 words
    for (int idx = tid; idx < WPK_WORDS; idx += 512) {
        int t = idx >> 5, o = idx & 31;       // t = p*9+kh*3+kw, o = oc pair
        float lo = wgt[(2 * o) * 144 + t];
        float hi = wgt[(2 * o + 1) * 144 + t];
        swpk[idx] = pack2(lo, hi);
    }
    __syncthreads();   // ssel ready

    // stage input tile (16 selected channels, 6x130 with halo, zero-padded)
    for (int idx = tid; idx < XS_FLOATS; idx += 512) {
        int p = idx / XS_CHSTRIDE;
        int rem = idx - p * XS_CHSTRIDE;
        int rr = rem / XS_ROWSTRIDE;
        int cc = rem - rr * XS_ROWSTRIDE;
        int gr = r0 + rr - 1, gc = c0 + cc - 1;
        float v = 0.0f;
        if ((unsigned)gr < 256u && (unsigned)gc < 256u)
            v = x[(((size_t)(b * C_ + ssel[p])) << 16) + (gr << 8) + gc];
        xs[idx] = v;
    }
    __syncthreads();

    const int ocg = tid & 3;
    const int pg  = tid >> 2;
    const int row = pg >> 5;
    const int wl  = pg & 31;

    unsigned long long acc[4][8];
    #pragma unroll
    for (int o = 0; o < 8; o++) {
        int oc0 = ocg * 16 + 2 * o;
        unsigned long long bz = pack2(__ldg(&bias[oc0]), __ldg(&bias[oc0 + 1]));
        #pragma unroll
        for (int i = 0; i < 4; i++) acc[i][o] = bz;
    }

    const float* xbase = xs + row * XS_ROWSTRIDE + wl;
    for (int p = 0; p < 16; p++) {
        const float* xp2 = xbase + p * XS_CHSTRIDE;
        #pragma unroll
        for (int kh = 0; kh < 3; kh++) {
            const float* xr = xp2 + kh * XS_ROWSTRIDE;
            #pragma unroll
            for (int kw = 0; kw < 3; kw++) {
                unsigned long long xd[4];
                #pragma unroll
                for (int i = 0; i < 4; i++) {
                    float xv = xr[kw + 32 * i];
                    xd[i] = pack2(xv, xv);
                }
                const unsigned long long* wr =
                    swpk + (((p * 9 + kh * 3 + kw) << 5) + (ocg << 3));
                #pragma unroll
                for (int o = 0; o < 8; o++) {
                    unsigned long long wv = wr[o];
                    #pragma unroll
                    for (int i = 0; i < 4; i++)
                        acc[i][o] = fma2(xd[i], wv, acc[i][o]);
                }
            }
        }
    }

    // store: per (o,i) warp writes 4 oc-planes x 8 consecutive floats (32B sectors)
    size_t outb = ((size_t)(b * OUTC_)) << 16;
    int prow = ((r0 + row) << 8) + c0 + wl;
    float* obase = out + outb + prow;
    #pragma unroll
    for (int o = 0; o < 8; o++) {
        int oc0 = ocg * 16 + 2 * o;
        float* o0 = obase + ((size_t)oc0 << 16);
        float* o1 = o0 + HW_;
        #pragma unroll
        for (int i = 0; i < 4; i++) {
            float lo, hi;
            unpack2(acc[i][o], lo, hi);
            o0[32 * i] = lo;
            o1[32 * i] = hi;
        }
    }
}

// ---------------- launch ----------------------------------------------------
extern "C" void kernel_launch(void* const* d_in, const int* in_sizes, int n_in,
                              void* d_out, int out_size) {
    (void)in_sizes; (void)n_in; (void)out_size;
    const float* x    = (const float*)d_in[0];
    const float* wgt  = (const float*)d_in[1];
    const float* bias = (const float*)d_in[2];
    float* out = (float*)d_out;

    cudaFuncSetAttribute(conv_copy_kernel,
                         cudaFuncAttributeMaxDynamicSharedMemorySize,
                         CONV_SMEM_BYTES);

    channel_stats_kernel<<<B_ * C_, 256>>>(x);
    topk_kernel<<<1, 8>>>();
    conv_copy_kernel<<<B_ * CU_ + B_ * 128, 512, CONV_SMEM_BYTES>>>(x, wgt, bias, out);
}